// round 17
// baseline (speedup 1.0000x reference)
#include <cuda_runtime.h>
#include <cuda_bf16.h>

typedef unsigned int       u32;
typedef unsigned long long u64;

#define BATCH 32
#define TQ    512
#define TK    2048
#define DIM   512

// ---------------------------------------------------------------------------
// Scratch. 2-section split storage: row = [hi(K) | lo(K)].
// Product = hi*hi + lo*hi + hi*lo (fp32 minus O(2^-18) lo*lo term)
// ---------------------------------------------------------------------------
__device__ __nv_bfloat16 g_Q2 [(size_t)BATCH * TQ  * 2 * DIM];  //  34 MB
__device__ __nv_bfloat16 g_E2 [(size_t)BATCH * TK  * 2 * DIM];  // 134 MB
__device__ float         g_S  [(size_t)BATCH * TQ  * TK];       // 134 MB
__device__ float2        g_stat[(size_t)BATCH * TQ * (TK / 128)]; // 2 MB

// ---------------------------------------------------------------------------
// Baseline-PTX tensor-core helpers
// ---------------------------------------------------------------------------
__device__ __forceinline__ u32 smem_u32(const void* p) {
    u32 a;
    asm("{ .reg .u64 t; cvta.to.shared.u64 t, %1; cvt.u32.u64 %0, t; }"
        : "=r"(a) : "l"(p));
    return a;
}

__device__ __forceinline__ void ldmatrix_x4(u32& r0, u32& r1, u32& r2, u32& r3,
                                            u32 addr) {
    asm volatile("ldmatrix.sync.aligned.m8n8.x4.shared.b16 {%0,%1,%2,%3}, [%4];"
                 : "=r"(r0), "=r"(r1), "=r"(r2), "=r"(r3) : "r"(addr));
}

__device__ __forceinline__ void ldmatrix_x4_trans(u32& r0, u32& r1, u32& r2, u32& r3,
                                                  u32 addr) {
    asm volatile("ldmatrix.sync.aligned.m8n8.x4.trans.shared.b16 {%0,%1,%2,%3}, [%4];"
                 : "=r"(r0), "=r"(r1), "=r"(r2), "=r"(r3) : "r"(addr));
}

__device__ __forceinline__ void mma_16816(float* c, const u32* a, const u32* b) {
    asm volatile(
        "mma.sync.aligned.m16n8k16.row.col.f32.bf16.bf16.f32 "
        "{%0,%1,%2,%3}, {%4,%5,%6,%7}, {%8,%9}, {%0,%1,%2,%3};"
        : "+f"(c[0]), "+f"(c[1]), "+f"(c[2]), "+f"(c[3])
        : "r"(a[0]), "r"(a[1]), "r"(a[2]), "r"(a[3]), "r"(b[0]), "r"(b[1]));
}

#define CP_ASYNC_16(saddr, gptr) \
    asm volatile("cp.async.cg.shared.global [%0], [%1], 16;" \
                 :: "r"(saddr), "l"(gptr) : "memory")
#define CP_COMMIT() asm volatile("cp.async.commit_group;" ::: "memory")
#define CP_WAIT(n)  asm volatile("cp.async.wait_group %0;" :: "n"(n) : "memory")

// ===========================================================================
// GEMM1 (chunk-major, fragment reuse, software-pipelined LDSM):
// S = Q @ E^T + softmax tile stats.
// Per 16-kstep: [al prefetched] MMA hi*hi -> [bl half] MMA lo*hi ->
//   [next ah/bh] MMA hi*lo(0-3) -> [bl half] MMA hi*lo(4-7).
// CTA 128x128, 3-stage cp.async, 8 warps (32m x 64n warp tiles).
// ===========================================================================
#define STAGES     3
#define ROWB       144
#define TILE_BYTES (128 * ROWB)
#define STAGE_BYTES (2 * TILE_BYTES)
#define GEMM_SMEM  (STAGES * STAGE_BYTES)    // 110592

__global__ void __launch_bounds__(256, 2)
gemm1_stats(const __nv_bfloat16* __restrict__ A, const __nv_bfloat16* __restrict__ B,
            float* __restrict__ C, float2* __restrict__ stat)
{
    extern __shared__ char smem[];
    const u32 smem_base = smem_u32(smem);

    constexpr int K   = DIM;
    constexpr int KT  = 2 * K;
    constexpr int NC  = K / 32;          // 16 chunks of 32k (hi+lo together)
    constexpr int N   = TK;

    const int tid = threadIdx.x;
    const int wid = tid >> 5;
    const int lid = tid & 31;
    const int wm  = wid & 3;
    const int wn  = wid >> 2;

    A += (long long)blockIdx.z * (TQ * (long long)KT);
    B += (long long)blockIdx.z * (TK * (long long)KT);
    C += (long long)blockIdx.z * ((long long)TQ * TK);
    const int m0 = blockIdx.y * 128;
    const int n0 = blockIdx.x * 128;

    const int q  = tid & 7;
    const int r0 = tid >> 3;
    const int gcol = ((q < 4) ? 0 : K) + (q & 3) * 8;

    const int a_off = (wm * 32 + (lid & 15)) * ROWB + ((lid >> 4) << 4);
    const int b_off = (wn * 64 + ((lid >> 4) << 3) + (lid & 7)) * ROWB +
                      (((lid >> 3) & 1) << 4);

    float acc[2][8][4];
#pragma unroll
    for (int mt = 0; mt < 2; mt++)
#pragma unroll
        for (int nt = 0; nt < 8; nt++)
#pragma unroll
            for (int j = 0; j < 4; j++) acc[mt][nt][j] = 0.0f;

    auto load_stage = [&](int s, int c) {
        const u32 sa = smem_base + s * STAGE_BYTES;
        const u32 sb = sa + TILE_BYTES;
        const __nv_bfloat16* Ap = A + (long long)(m0 + r0) * KT + gcol + c * 32;
        const __nv_bfloat16* Bp = B + (long long)(n0 + r0) * KT + gcol + c * 32;
#pragma unroll
        for (int i = 0; i < 4; i++) {
            CP_ASYNC_16(sa + (r0 + i * 32) * ROWB + q * 16, Ap + (long long)(i * 32) * KT);
            CP_ASYNC_16(sb + (r0 + i * 32) * ROWB + q * 16, Bp + (long long)(i * 32) * KT);
        }
    };

    load_stage(0, 0); CP_COMMIT();
    load_stage(1, 1); CP_COMMIT();

    int sc = 0, sl = 2;
    for (int c = 0; c < NC; c++) {
        CP_WAIT(1);
        __syncthreads();

        if (c + 2 < NC) load_stage(sl, c + 2);
        CP_COMMIT();

        const u32 sa = smem_base + sc * STAGE_BYTES;
        const u32 sb = sa + TILE_BYTES;

        u32 ah[2][2][4];   // A_hi, double-buffered across ksteps
        u32 bh[16];        // B_hi (single buffer; dead after lo*hi)
        u32 al[2][4];      // A_lo
        u32 bl[8];         // B_lo half-buffer (2 bt at a time)

        // chunk prologue: ks0 hi fragments
        ldmatrix_x4(ah[0][0][0], ah[0][0][1], ah[0][0][2], ah[0][0][3], sa + a_off);
        ldmatrix_x4(ah[0][1][0], ah[0][1][1], ah[0][1][2], ah[0][1][3],
                    sa + a_off + 16 * ROWB);
#pragma unroll
        for (int bt = 0; bt < 4; bt++)
            ldmatrix_x4(bh[4 * bt], bh[4 * bt + 1], bh[4 * bt + 2], bh[4 * bt + 3],
                        sb + b_off + bt * 16 * ROWB);

#pragma unroll
        for (int ks = 0; ks < 2; ks++) {
            const int cb = ks;
            const int ko = ks * 32;

            // load A_lo (used by lo*hi below)
            ldmatrix_x4(al[0][0], al[0][1], al[0][2], al[0][3],
                        sa + a_off + 64 + ko);
            ldmatrix_x4(al[1][0], al[1][1], al[1][2], al[1][3],
                        sa + a_off + 64 + ko + 16 * ROWB);

            // MMA hi*hi
#pragma unroll
            for (int mt = 0; mt < 2; mt++)
#pragma unroll
                for (int nt = 0; nt < 8; nt++)
                    mma_16816(acc[mt][nt], ah[cb][mt], &bh[2 * nt]);

            // load B_lo first half (bt 0,1) — used by hi*lo nt0-3
#pragma unroll
            for (int bt = 0; bt < 2; bt++)
                ldmatrix_x4(bl[4 * bt], bl[4 * bt + 1], bl[4 * bt + 2], bl[4 * bt + 3],
                            sb + b_off + bt * 16 * ROWB + 64 + ko);

            // MMA lo*hi (B_hi reused; last use of bh)
#pragma unroll
            for (int mt = 0; mt < 2; mt++)
#pragma unroll
                for (int nt = 0; nt < 8; nt++)
                    mma_16816(acc[mt][nt], al[mt], &bh[2 * nt]);

            // prefetch next kstep's hi fragments (bh free now; ah into buf 1)
            if (ks == 0) {
                ldmatrix_x4(ah[1][0][0], ah[1][0][1], ah[1][0][2], ah[1][0][3],
                            sa + a_off + 32);
                ldmatrix_x4(ah[1][1][0], ah[1][1][1], ah[1][1][2], ah[1][1][3],
                            sa + a_off + 32 + 16 * ROWB);
#pragma unroll
                for (int bt = 0; bt < 4; bt++)
                    ldmatrix_x4(bh[4 * bt], bh[4 * bt + 1], bh[4 * bt + 2], bh[4 * bt + 3],
                                sb + b_off + bt * 16 * ROWB + 32);
            }

            // MMA hi*lo, first half (nt 0-3)
#pragma unroll
            for (int mt = 0; mt < 2; mt++)
#pragma unroll
                for (int nt = 0; nt < 4; nt++)
                    mma_16816(acc[mt][nt], ah[cb][mt], &bl[2 * nt]);

            // load B_lo second half (bt 2,3)
#pragma unroll
            for (int bt = 0; bt < 2; bt++)
                ldmatrix_x4(bl[4 * bt], bl[4 * bt + 1], bl[4 * bt + 2], bl[4 * bt + 3],
                            sb + b_off + (bt + 2) * 16 * ROWB + 64 + ko);

            // MMA hi*lo, second half (nt 4-7)
#pragma unroll
            for (int mt = 0; mt < 2; mt++)
#pragma unroll
                for (int nt = 4; nt < 8; nt++)
                    mma_16816(acc[mt][nt], ah[cb][mt], &bl[2 * (nt - 4)]);
        }

        sc = (sc + 1 == STAGES) ? 0 : sc + 1;
        sl = (sl + 1 == STAGES) ? 0 : sl + 1;
    }

    // ---- store S ----
#pragma unroll
    for (int mt = 0; mt < 2; mt++) {
        const int row = m0 + wm * 32 + mt * 16 + (lid >> 2);
#pragma unroll
        for (int nt = 0; nt < 8; nt++) {
            const int col = n0 + wn * 64 + nt * 8 + ((lid & 3) << 1);
            *(float2*)(C + (long long)row * N + col) =
                make_float2(acc[mt][nt][0], acc[mt][nt][1]);
            *(float2*)(C + (long long)(row + 8) * N + col) =
                make_float2(acc[mt][nt][2], acc[mt][nt][3]);
        }
    }

    // ---- softmax tile stats ----
    CP_WAIT(0);
    __syncthreads();
    float* smax = (float*)smem;
    float* ssum = (float*)(smem + 1024);

    float mrow[2][2];
#pragma unroll
    for (int mt = 0; mt < 2; mt++)
#pragma unroll
        for (int h = 0; h < 2; h++) {
            float m = -3.0e38f;
#pragma unroll
            for (int nt = 0; nt < 8; nt++)
                m = fmaxf(m, fmaxf(acc[mt][nt][2 * h], acc[mt][nt][2 * h + 1]));
            m = fmaxf(m, __shfl_xor_sync(0xffffffffu, m, 1));
            m = fmaxf(m, __shfl_xor_sync(0xffffffffu, m, 2));
            const int rloc = wm * 32 + mt * 16 + h * 8 + (lid >> 2);
            if ((lid & 3) == 0) smax[wn * 128 + rloc] = m;
        }
    __syncthreads();
#pragma unroll
    for (int mt = 0; mt < 2; mt++)
#pragma unroll
        for (int h = 0; h < 2; h++) {
            const int rloc = wm * 32 + mt * 16 + h * 8 + (lid >> 2);
            mrow[mt][h] = fmaxf(smax[rloc], smax[128 + rloc]);
            float s = 0.0f;
#pragma unroll
            for (int nt = 0; nt < 8; nt++)
                s += __expf(acc[mt][nt][2 * h] - mrow[mt][h]) +
                     __expf(acc[mt][nt][2 * h + 1] - mrow[mt][h]);
            s += __shfl_xor_sync(0xffffffffu, s, 1);
            s += __shfl_xor_sync(0xffffffffu, s, 2);
            if ((lid & 3) == 0) ssum[wn * 128 + rloc] = s;
        }
    __syncthreads();
    if (wn == 0 && (lid & 3) == 0) {
#pragma unroll
        for (int mt = 0; mt < 2; mt++)
#pragma unroll
            for (int h = 0; h < 2; h++) {
                const int rloc = wm * 32 + mt * 16 + h * 8 + (lid >> 2);
                const long long row = (long long)blockIdx.z * TQ + m0 + rloc;
                stat[row * 16 + blockIdx.x] =
                    make_float2(mrow[mt][h], ssum[rloc] + ssum[128 + rloc]);
            }
    }
}

// ===========================================================================
// GEMM2 (fused softmax): O = softmax(S) @ E.  R15/R16 mainloop verbatim;
// rowstat reduction folded into the prologue (16 L2-resident tile stats/row).
// ===========================================================================
#define ROWB2A 272                          // A row stride
#define ROWB2B 560                          // B row stride (512 data + 48 pad)
#define A2_ST  (64 * ROWB2A)                // 17408
#define B2_ST  (64 * ROWB2B)                // 35840
#define STG2   (A2_ST + B2_ST)              // 53248
#define GEMM2_SMEM (2 * STG2)               // 106496

__global__ void __launch_bounds__(256, 2)
gemm2_fused(const float* __restrict__ S, const __nv_bfloat16* __restrict__ E2,
            const float2* __restrict__ stat, float* __restrict__ O)
{
    extern __shared__ char smem[];
    const u32 smem_base = smem_u32(smem);

    constexpr int NC = TK / 64;   // 32 chunks

    const int tid = threadIdx.x;
    const int wid = tid >> 5;
    const int lid = tid & 31;
    const int wm  = wid & 1;      // 2 warps along M (32 rows)
    const int wn  = wid >> 1;     // 4 warps along N (32 cols)

    const int bz = blockIdx.z;
    const int m0 = blockIdx.y * 64;
    const int n0 = blockIdx.x * 128;

    const int ar = tid >> 2;
    const int aq = tid & 3;
    const float* Ap = S + ((long long)bz * TQ + m0 + ar) * TK + aq * 16;

    // ---- inline rowstat: merge 16 tile stats for row (m0+ar) ----
    float m_r, inv_r;
    {
        const float2* t = stat + ((long long)bz * TQ + m0 + ar) * 16;
        float m = t[0].x;
#pragma unroll
        for (int i = 1; i < 16; i++) m = fmaxf(m, t[i].x);
        float s = 0.0f;
#pragma unroll
        for (int i = 0; i < 16; i++) s += t[i].y * __expf(t[i].x - m);
        m_r = m;
        inv_r = 1.0f / s;
    }

    const int br = tid >> 2;
    const int bq = tid & 3;
    const __nv_bfloat16* Bp = E2 + ((long long)bz * TK + br) * (2 * DIM);

    const int a_base = (wm * 32 + (lid & 15)) * ROWB2A + ((lid >> 4) << 4);
    const int b_base = (lid & 15) * ROWB2B + ((lid >> 4) << 4) + wn * 64;

    float acc[2][4][4];
#pragma unroll
    for (int mt = 0; mt < 2; mt++)
#pragma unroll
        for (int nt = 0; nt < 4; nt++)
#pragma unroll
            for (int j = 0; j < 4; j++) acc[mt][nt][j] = 0.0f;

    float4 av[4];

    auto lda = [&](int c) {
#pragma unroll
        for (int i = 0; i < 4; i++) av[i] = *(const float4*)(Ap + c * 64 + i * 4);
    };
    auto ldb = [&](int st, int c) {
        const u32 sb = smem_base + st * STG2 + A2_ST;
        const __nv_bfloat16* src = Bp + (long long)c * 64 * (2 * DIM);
#pragma unroll
        for (int i = 0; i < 8; i++) {
            const int cc = bq + 4 * i;
            const int go = (cc < 16) ? (n0 + cc * 8) : (DIM + n0 + (cc - 16) * 8);
            CP_ASYNC_16(sb + br * ROWB2B + cc * 16, src + go);
        }
    };
    auto cvta = [&](int st) {
        char* dst = smem + st * STG2 + ar * ROWB2A + aq * 32;
        u32 hi[8], lo[8];
        const float* f = (const float*)av;
#pragma unroll
        for (int j = 0; j < 8; j++) {
            const float p0 = __expf(f[2 * j]     - m_r) * inv_r;
            const float p1 = __expf(f[2 * j + 1] - m_r) * inv_r;
            const __nv_bfloat16 h0 = __float2bfloat16(p0);
            const __nv_bfloat16 h1 = __float2bfloat16(p1);
            const __nv_bfloat16 l0 = __float2bfloat16(p0 - __bfloat162float(h0));
            const __nv_bfloat16 l1 = __float2bfloat16(p1 - __bfloat162float(h1));
            __nv_bfloat162 hh, ll;
            hh.x = h0; hh.y = h1; ll.x = l0; ll.y = l1;
            hi[j] = *(u32*)&hh; lo[j] = *(u32*)&ll;
        }
        *(uint4*)(dst)            = make_uint4(hi[0], hi[1], hi[2], hi[3]);
        *(uint4*)(dst + 16)       = make_uint4(hi[4], hi[5], hi[6], hi[7]);
        *(uint4*)(dst + 128)      = make_uint4(lo[0], lo[1], lo[2], lo[3]);
        *(uint4*)(dst + 128 + 16) = make_uint4(lo[4], lo[5], lo[6], lo[7]);
    };

    lda(0);
    ldb(0, 0); CP_COMMIT();
    cvta(0);

    for (int c = 0; c < NC; c++) {
        CP_WAIT(0);
        __syncthreads();

        if (c + 1 < NC) {
            lda(c + 1);
            ldb((c + 1) & 1, c + 1);
            CP_COMMIT();
        }

        const u32 sa = smem_base + (c & 1) * STG2;
        const u32 sb = sa + A2_ST;

        u32 ah[2][2][4];
        u32 bh[2][8];
        u32 al[2][4];
        u32 bl[8];

        ldmatrix_x4(ah[0][0][0], ah[0][0][1], ah[0][0][2], ah[0][0][3], sa + a_base);
        ldmatrix_x4(ah[0][1][0], ah[0][1][1], ah[0][1][2], ah[0][1][3],
                    sa + a_base + 16 * ROWB2A);
        ldmatrix_x4_trans(bh[0][0], bh[0][1], bh[0][2], bh[0][3], sb + b_base);
        ldmatrix_x4_trans(bh[0][4], bh[0][5], bh[0][6], bh[0][7], sb + b_base + 32);

#pragma unroll
        for (int ks = 0; ks < 4; ks++) {
            const int cb = ks & 1, nb = cb ^ 1;
            const int aoff = ks * 32;
            const int boff = ks * 16 * ROWB2B;

            ldmatrix_x4(al[0][0], al[0][1], al[0][2], al[0][3],
                        sa + a_base + 128 + aoff);
            ldmatrix_x4(al[1][0], al[1][1], al[1][2], al[1][3],
                        sa + a_base + 128 + aoff + 16 * ROWB2A);
#pragma unroll
            for (int mt = 0; mt < 2; mt++)
#pragma unroll
                for (int nt = 0; nt < 4; nt++)
                    mma_16816(acc[mt][nt], ah[cb][mt], &bh[cb][2 * nt]);

            ldmatrix_x4_trans(bl[0], bl[1], bl[2], bl[3],
                              sb + b_base + boff + 256);
            ldmatrix_x4_trans(bl[4], bl[5], bl[6], bl[7],
                              sb + b_base + boff + 256 + 32);
#pragma unroll
            for (int mt = 0; mt < 2; mt++)
#pragma unroll
                for (int nt = 0; nt < 4; nt++)
                    mma_16816(acc[mt][nt], al[mt], &bh[cb][2 * nt]);

            if (ks < 3) {
                ldmatrix_x4(ah[nb][0][0], ah[nb][0][1], ah[nb][0][2], ah[nb][0][3],
                            sa + a_base + aoff + 32);
                ldmatrix_x4(ah[nb][1][0], ah[nb][1][1], ah[nb][1][2], ah[nb][1][3],
                            sa + a_base + aoff + 32 + 16 * ROWB2A);
                ldmatrix_x4_trans(bh[nb][0], bh[nb][1], bh[nb][2], bh[nb][3],
                                  sb + b_base + boff + 16 * ROWB2B);
                ldmatrix_x4_trans(bh[nb][4], bh[nb][5], bh[nb][6], bh[nb][7],
                                  sb + b_base + boff + 16 * ROWB2B + 32);
            }
#pragma unroll
            for (int mt = 0; mt < 2; mt++)
#pragma unroll
                for (int nt = 0; nt < 4; nt++)
                    mma_16816(acc[mt][nt], ah[cb][mt], &bl[2 * nt]);
        }

        if (c + 1 < NC) cvta((c + 1) & 1);
    }

    O += (long long)bz * TQ * DIM;
#pragma unroll
    for (int mt = 0; mt < 2; mt++) {
        const int row = m0 + wm * 32 + mt * 16 + (lid >> 2);
#pragma unroll
        for (int nt = 0; nt < 4; nt++) {
            const int col = n0 + wn * 32 + nt * 8 + ((lid & 3) << 1);
            *(float2*)(O + (long long)row * DIM + col) =
                make_float2(acc[mt][nt][0], acc[mt][nt][1]);
            *(float2*)(O + (long long)(row + 8) * DIM + col) =
                make_float2(acc[mt][nt][2], acc[mt][nt][3]);
        }
    }
}

// ---------------------------------------------------------------------------
// Row-wise hi/lo split (used for both Q and E)
// ---------------------------------------------------------------------------
template <int K>
__global__ void __launch_bounds__(256)
split2_kernel(const float* __restrict__ in, __nv_bfloat16* __restrict__ out,
              long long total)
{
    const long long n4 = total >> 2;
    for (long long i = (long long)blockIdx.x * blockDim.x + threadIdx.x;
         i < n4; i += (long long)gridDim.x * blockDim.x) {
        const long long e = i << 2;
        const long long r = e / K;
        const int k = (int)(e - r * (long long)K);
        const float4 x = *(const float4*)(in + e);
        const float xs[4] = {x.x, x.y, x.z, x.w};
        __nv_bfloat16 h[4], l[4];
#pragma unroll
        for (int j = 0; j < 4; j++) {
            h[j] = __float2bfloat16(xs[j]);
            l[j] = __float2bfloat16(xs[j] - __bfloat162float(h[j]));
        }
        __nv_bfloat16* o = out + r * (2LL * K) + k;
        __nv_bfloat162 hh0, hh1, ll0, ll1;
        hh0.x = h[0]; hh0.y = h[1]; hh1.x = h[2]; hh1.y = h[3];
        ll0.x = l[0]; ll0.y = l[1]; ll1.x = l[2]; ll1.y = l[3];
        *(__nv_bfloat162*)(o + 0)     = hh0;
        *(__nv_bfloat162*)(o + 2)     = hh1;
        *(__nv_bfloat162*)(o + K)     = ll0;
        *(__nv_bfloat162*)(o + K + 2) = ll1;
    }
}

// ---------------------------------------------------------------------------
// Entry point
// ---------------------------------------------------------------------------
extern "C" void kernel_launch(void* const* d_in, const int* in_sizes, int n_in,
                              void* d_out, int out_size)
{
    const float* Q = (const float*)d_in[0];
    const float* E = (const float*)d_in[1];
    float* O = (float*)d_out;

    __nv_bfloat16 *Q2, *E2;
    float* S;
    float2 *stat;
    cudaGetSymbolAddress((void**)&Q2,   g_Q2);
    cudaGetSymbolAddress((void**)&E2,   g_E2);
    cudaGetSymbolAddress((void**)&S,    g_S);
    cudaGetSymbolAddress((void**)&stat, g_stat);

    cudaFuncSetAttribute(gemm1_stats, cudaFuncAttributeMaxDynamicSharedMemorySize, GEMM_SMEM);
    cudaFuncSetAttribute(gemm2_fused, cudaFuncAttributeMaxDynamicSharedMemorySize, GEMM2_SMEM);

    // operand conversions
    split2_kernel<DIM><<<8192, 256>>>(Q, Q2, (long long)BATCH * TQ * DIM);
    split2_kernel<DIM><<<32768, 256>>>(E, E2, (long long)BATCH * TK * DIM);

    // S = Q @ E^T  + per-tile softmax stats (pipelined fragment-reuse mainloop)
    gemm1_stats<<<dim3(TK / 128, TQ / 128, BATCH), 256, GEMM_SMEM>>>(Q2, E2, S, stat);

    // O = softmax(S) @ E  (rowstat folded into prologue)
    gemm2_fused<<<dim3(DIM / 128, TQ / 64, BATCH), 256, GEMM2_SMEM>>>(S, E2, stat, O);
}